// round 6
// baseline (speedup 1.0000x reference)
#include <cuda_runtime.h>
#include <cuda_fp16.h>
#include <cstdint>
#include <math.h>

#define Bb 16
#define Nn 1024
#define Dd 1024
#define Hh 8
#define HDd 128
#define SCALE_F 0.08838834764831845f   // 1/sqrt(128)
#define NEG_F  -1e30f

// ---------------- scratch (static; no allocation allowed) ----------------
__device__ __align__(16) __half g_x16 [Bb*Nn*Dd];     // fp16 copy of x
__device__ __align__(16) __half g_Wq16[Hh*Dd*HDd];
__device__ __align__(16) __half g_Wk16[Hh*Dd*HDd];
__device__ __align__(16) __half g_Wv16[Hh*Dd*HDd];
__device__ __align__(16) __half g_Wfc16[Dd*Dd];
__device__ __align__(16) __half g_Q[Bb*Hh*Nn*HDd];    // [B,H,N,HD]
__device__ __align__(16) __half g_K[Bb*Hh*Nn*HDd];
__device__ __align__(16) __half g_V[Bb*Hh*Nn*HDd];
__device__ __align__(16) __half g_O16[Bb*Nn*Dd];      // [B,N,D]

// ---------------- helpers ----------------
__device__ __forceinline__ uint32_t smaddr(const void* p) {
    return (uint32_t)__cvta_generic_to_shared(p);
}
__device__ __forceinline__ void ldsm4(uint32_t& r0, uint32_t& r1, uint32_t& r2, uint32_t& r3, uint32_t a) {
    asm volatile("ldmatrix.sync.aligned.m8n8.x4.shared.b16 {%0,%1,%2,%3}, [%4];"
                 : "=r"(r0), "=r"(r1), "=r"(r2), "=r"(r3) : "r"(a));
}
__device__ __forceinline__ void ldsm4t(uint32_t& r0, uint32_t& r1, uint32_t& r2, uint32_t& r3, uint32_t a) {
    asm volatile("ldmatrix.sync.aligned.m8n8.x4.trans.shared.b16 {%0,%1,%2,%3}, [%4];"
                 : "=r"(r0), "=r"(r1), "=r"(r2), "=r"(r3) : "r"(a));
}
__device__ __forceinline__ void mma16(float c[4], const uint32_t a[4], const uint32_t b[2]) {
    asm volatile(
        "mma.sync.aligned.m16n8k16.row.col.f32.f16.f16.f32 "
        "{%0,%1,%2,%3}, {%4,%5,%6,%7}, {%8,%9}, {%0,%1,%2,%3};"
        : "+f"(c[0]), "+f"(c[1]), "+f"(c[2]), "+f"(c[3])
        : "r"(a[0]), "r"(a[1]), "r"(a[2]), "r"(a[3]), "r"(b[0]), "r"(b[1]));
}
__device__ __forceinline__ uint32_t packh2(float a, float b) {
    __half2 h = __floats2half2_rn(a, b);
    return *(uint32_t*)&h;
}

#define CP16(dst_sm, src_g) \
    asm volatile("cp.async.cg.shared.global [%0], [%1], 16;" :: "r"(dst_sm), "l"(src_g))
#define CP_COMMIT() asm volatile("cp.async.commit_group;")
#define CP_WAIT0()  asm volatile("cp.async.wait_group 0;")
#define CP_WAIT1()  asm volatile("cp.async.wait_group 1;")

// ============================================================
// Kernel 0: convert fp32 inputs to fp16 scratch
// ============================================================
#define CV_X  4194304           // float4 counts
#define CV_W  262144
__global__ __launch_bounds__(256) void convert_all(
    const float* __restrict__ x,  const float* __restrict__ Wq,
    const float* __restrict__ Wk, const float* __restrict__ Wv,
    const float* __restrict__ Wfc)
{
    const int total = CV_X + 4*CV_W;
    for (int i = blockIdx.x * blockDim.x + threadIdx.x; i < total; i += gridDim.x * blockDim.x) {
        const float* src; __half* dst; int off;
        if (i < CV_X)                 { src = x;   dst = g_x16;  off = i; }
        else if (i < CV_X + CV_W)     { src = Wq;  dst = g_Wq16; off = i - CV_X; }
        else if (i < CV_X + 2*CV_W)   { src = Wk;  dst = g_Wk16; off = i - CV_X - CV_W; }
        else if (i < CV_X + 3*CV_W)   { src = Wv;  dst = g_Wv16; off = i - CV_X - 2*CV_W; }
        else                          { src = Wfc; dst = g_Wfc16; off = i - CV_X - 3*CV_W; }
        float4 v = ((const float4*)src)[off];
        uint2 u;
        u.x = packh2(v.x, v.y);
        u.y = packh2(v.z, v.w);
        ((uint2*)dst)[off] = u;
    }
}

// ============================================================
// GEMM smem geometry: 3-stage, k-depth 64, CTA tile 128x128
// ============================================================
#define A_ST 9216     // 128 * 72 halves
#define B_ST 8704     // 64 * 136 halves
#define GEMM_SMEM ((3*(A_ST + B_ST)) * 2)

// Shared 3-stage + A-prefetch mainloop body.  Requires in scope:
//   t, lane, warp, wm, wn, acc[2][8][4], As, Bs (stage-0 base pointers),
//   lambda load_stage(k0, st) that commits one cp.async group.
#define GEMM_MAINLOOP()                                                                 \
    load_stage(0, 0);                                                                   \
    load_stage(64, 1);                                                                  \
    const int rowA = (lane & 15) * 72 + ((lane >> 4) << 3);                             \
    const int rowB = ((lane >> 3) & 1) * 8 * 136 + (lane & 7) * 136 + (lane >> 4) * 8;  \
    for (int s = 0; s < 16; s++) {                                                      \
        if (s < 15) { CP_WAIT1(); } else { CP_WAIT0(); }                                \
        __syncthreads();                                                                \
        if (s < 14) load_stage((s + 2) * 64, (s + 2) % 3);                              \
        const __half* Ac = As + (s % 3) * A_ST + wm * 32 * 72;                          \
        const __half* Bc = Bs + (s % 3) * B_ST + wn * 64;                               \
        uint32_t ac[2][4], an[2][4];                                                    \
        _Pragma("unroll")                                                               \
        for (int mt = 0; mt < 2; mt++)                                                  \
            ldsm4(ac[mt][0], ac[mt][1], ac[mt][2], ac[mt][3],                           \
                  smaddr(Ac + mt * 16 * 72 + rowA));                                    \
        _Pragma("unroll")                                                               \
        for (int ks = 0; ks < 4; ks++) {                                                \
            int kk = ks * 16;                                                           \
            if (ks < 3) {                                                               \
                _Pragma("unroll")                                                       \
                for (int mt = 0; mt < 2; mt++)                                          \
                    ldsm4(an[mt][0], an[mt][1], an[mt][2], an[mt][3],                   \
                          smaddr(Ac + mt * 16 * 72 + rowA + kk + 16));                  \
            }                                                                           \
            uint32_t bf[8][2];                                                          \
            _Pragma("unroll")                                                           \
            for (int nb = 0; nb < 2; nb++) {                                            \
                uint32_t r0, r1, r2, r3;                                                \
                ldsm4t(r0, r1, r2, r3, smaddr(Bc + kk * 136 + rowB + nb * 16));         \
                bf[nb * 2][0] = r0; bf[nb * 2][1] = r1;                                 \
                bf[nb * 2 + 1][0] = r2; bf[nb * 2 + 1][1] = r3;                         \
            }                                                                           \
            _Pragma("unroll")                                                           \
            for (int mt = 0; mt < 2; mt++)                                              \
                _Pragma("unroll")                                                       \
                for (int nt = 0; nt < 4; nt++)                                          \
                    mma16(acc[mt][nt], ac[mt], bf[nt]);                                 \
            _Pragma("unroll")                                                           \
            for (int nb = 2; nb < 4; nb++) {                                            \
                uint32_t r0, r1, r2, r3;                                                \
                ldsm4t(r0, r1, r2, r3, smaddr(Bc + kk * 136 + rowB + nb * 16));         \
                bf[nb * 2][0] = r0; bf[nb * 2][1] = r1;                                 \
                bf[nb * 2 + 1][0] = r2; bf[nb * 2 + 1][1] = r3;                         \
            }                                                                           \
            _Pragma("unroll")                                                           \
            for (int mt = 0; mt < 2; mt++)                                              \
                _Pragma("unroll")                                                       \
                for (int nt = 4; nt < 8; nt++)                                          \
                    mma16(acc[mt][nt], ac[mt], bf[nt]);                                 \
            if (ks < 3) {                                                               \
                _Pragma("unroll")                                                       \
                for (int mt = 0; mt < 2; mt++)                                          \
                    _Pragma("unroll")                                                   \
                    for (int i = 0; i < 4; i++) ac[mt][i] = an[mt][i];                  \
            }                                                                           \
        }                                                                               \
    }

// ============================================================
// Kernel 1: fused QKV projection (fp16 in, fp16 out)
// grid (128 m-tiles, 1, 24 = proj*8+head), block 256
// ============================================================
__global__ __launch_bounds__(256, 2) void qkv_gemm(
    const float* __restrict__ bq, const float* __restrict__ bk, const float* __restrict__ bv)
{
    extern __shared__ __half sm[];
    __half* As = sm;                // [3][128][72]
    __half* Bs = sm + 3*A_ST;       // [3][64][136]

    const int z = blockIdx.z;
    const int p = z >> 3;
    const int h = z & 7;
    const __half* W   = (p == 0 ? g_Wq16 : (p == 1 ? g_Wk16 : g_Wv16)) + (size_t)h * Dd * HDd;
    const float* bias = (p == 0 ? bq : (p == 1 ? bk : bv)) + h * HDd;
    __half* Cout      = (p == 0 ? g_Q : (p == 1 ? g_K : g_V));

    const int m0   = blockIdx.x * 128;
    const int t    = threadIdx.x;
    const int lane = t & 31;
    const int warp = t >> 5;
    const int g    = lane >> 2;
    const int tg   = lane & 3;
    const int wm   = warp >> 1;
    const int wn   = warp & 1;

    float acc[2][8][4];
#pragma unroll
    for (int mt = 0; mt < 2; mt++)
#pragma unroll
        for (int nt = 0; nt < 8; nt++)
#pragma unroll
            for (int i = 0; i < 4; i++) acc[mt][nt][i] = 0.f;

    auto load_stage = [&](int k0, int st) {
        __half* Ad = As + st * A_ST;
        __half* Bd = Bs + st * B_ST;
#pragma unroll
        for (int pp = 0; pp < 4; pp++) {
            int idx = t + pp * 256;
            int r = idx >> 3, c = (idx & 7) * 8;
            CP16(smaddr(Ad + r * 72 + c), g_x16 + (size_t)(m0 + r) * Dd + k0 + c);
        }
#pragma unroll
        for (int pp = 0; pp < 4; pp++) {
            int idx = t + pp * 256;
            int r = idx >> 4, c = (idx & 15) * 8;
            CP16(smaddr(Bd + r * 136 + c), W + (size_t)(k0 + r) * HDd + c);
        }
        CP_COMMIT();
    };

    GEMM_MAINLOOP()

    // epilogue -> [B,H,N,HD] fp16 (+bias)
#pragma unroll
    for (int mt = 0; mt < 2; mt++) {
#pragma unroll
        for (int half = 0; half < 2; half++) {
            int r  = m0 + wm * 32 + mt * 16 + g + half * 8;
            int bb = r >> 10;
            int n  = r & 1023;
            __half* dst = Cout + (((size_t)(bb * Hh + h)) * Nn + n) * HDd;
#pragma unroll
            for (int nt = 0; nt < 8; nt++) {
                int cc = wn * 64 + nt * 8 + 2 * tg;
                *(half2*)(dst + cc) = __floats2half2_rn(
                    acc[mt][nt][half * 2 + 0] + bias[cc],
                    acc[mt][nt][half * 2 + 1] + bias[cc + 1]);
            }
        }
    }
}

// ============================================================
// Kernel 2: flash attention, warp-private softmax, P in regs
// grid (8 q-tiles, 8 heads, 16 batch), block 256 (8 warps x 16 rows)
// ============================================================
#define Q_SZ  17408            // 128*136 halves
#define KV_ST 8704             // 64*136 halves
#define ATTN_SMEM_BYTES ((Q_SZ + 4*KV_ST)*2 + 2*64*4)

__global__ __launch_bounds__(256) void attn_kernel(const int* __restrict__ x_mask)
{
    extern __shared__ __half sm[];
    __half* Qs = sm;                    // [128][136]
    __half* Ks = sm + Q_SZ;             // [2][64][136]
    __half* Vs = Ks + 2 * KV_ST;        // [2][64][136]
    int*    km = (int*)(Vs + 2 * KV_ST);// [2][64]

    const int qt = blockIdx.x, h = blockIdx.y, b = blockIdx.z;
    const int t    = threadIdx.x;
    const int lane = t & 31;
    const int warp = t >> 5;
    const int g    = lane >> 2;
    const int tg   = lane & 3;
    const size_t bh = ((size_t)b * Hh + h) * Nn;
    const int q0 = qt * 128;
    const int rA = warp * 16 + g;
    const int rB = rA + 8;

#pragma unroll
    for (int pp = 0; pp < 8; pp++) {
        int idx = t + pp * 256;
        int r = idx >> 4, c = (idx & 15) * 8;
        CP16(smaddr(Qs + r * 136 + c), g_Q + (bh + q0 + r) * HDd + c);
    }
    auto load_kv = [&](int kt, int st) {
        int k0 = kt * 64;
        __half* Kd = Ks + st * KV_ST;
        __half* Vd = Vs + st * KV_ST;
#pragma unroll
        for (int pp = 0; pp < 4; pp++) {
            int idx = t + pp * 256;
            int r = idx >> 4, c = (idx & 15) * 8;
            CP16(smaddr(Kd + r * 136 + c), g_K + (bh + k0 + r) * HDd + c);
            CP16(smaddr(Vd + r * 136 + c), g_V + (bh + k0 + r) * HDd + c);
        }
        if (t < 64) km[st * 64 + t] = x_mask[b * Nn + k0 + t];
    };
    load_kv(0, 0);
    CP_COMMIT();

    const int qmA = x_mask[b * Nn + q0 + rA];
    const int qmB = x_mask[b * Nn + q0 + rB];
    float mA = -INFINITY, mB = -INFINITY, lA = 0.f, lB = 0.f;

    float o[16][4];
#pragma unroll
    for (int jj = 0; jj < 16; jj++)
#pragma unroll
        for (int i = 0; i < 4; i++) o[jj][i] = 0.f;

    for (int kt = 0; kt < 16; kt++) {
        const int cur = kt & 1;
        if (kt < 15) { load_kv(kt + 1, cur ^ 1); CP_COMMIT(); CP_WAIT1(); }
        else         { CP_WAIT0(); }
        __syncthreads();

        const __half* Kst = Ks + cur * KV_ST;
        const __half* Vst = Vs + cur * KV_ST;
        const int*    kmc = km + cur * 64;

        float s[8][4];
#pragma unroll
        for (int nt = 0; nt < 8; nt++)
#pragma unroll
            for (int i = 0; i < 4; i++) s[nt][i] = 0.f;

#pragma unroll
        for (int ks = 0; ks < 8; ks++) {
            int kk = ks * 16;
            uint32_t a[4];
            ldsm4(a[0], a[1], a[2], a[3],
                  smaddr(Qs + (warp * 16 + (lane & 15)) * 136 + kk + ((lane >> 4) << 3)));
#pragma unroll
            for (int nb = 0; nb < 4; nb++) {
                int n0 = nb * 16;
                uint32_t r0, r1, r2, r3;
                ldsm4(r0, r1, r2, r3,
                      smaddr(Kst + (n0 + ((lane >> 4) << 3) + (lane & 7)) * 136 + kk + ((lane >> 3) & 1) * 8));
                uint32_t b0[2] = { r0, r1 }, b1[2] = { r2, r3 };
                mma16(s[nb * 2], a, b0);
                mma16(s[nb * 2 + 1], a, b1);
            }
        }

#pragma unroll
        for (int nt = 0; nt < 8; nt++) {
            int c0 = nt * 8 + 2 * tg;
            int k0m = kmc[c0], k1m = kmc[c0 + 1];
            s[nt][0] = (qmA & k0m) ? s[nt][0] * SCALE_F : NEG_F;
            s[nt][1] = (qmA & k1m) ? s[nt][1] * SCALE_F : NEG_F;
            s[nt][2] = (qmB & k0m) ? s[nt][2] * SCALE_F : NEG_F;
            s[nt][3] = (qmB & k1m) ? s[nt][3] * SCALE_F : NEG_F;
        }

        float tmA = s[0][0], tmB = s[0][2];
#pragma unroll
        for (int nt = 0; nt < 8; nt++) {
            tmA = fmaxf(tmA, fmaxf(s[nt][0], s[nt][1]));
            tmB = fmaxf(tmB, fmaxf(s[nt][2], s[nt][3]));
        }
        tmA = fmaxf(tmA, __shfl_xor_sync(0xffffffffu, tmA, 1));
        tmA = fmaxf(tmA, __shfl_xor_sync(0xffffffffu, tmA, 2));
        tmB = fmaxf(tmB, __shfl_xor_sync(0xffffffffu, tmB, 1));
        tmB = fmaxf(tmB, __shfl_xor_sync(0xffffffffu, tmB, 2));

        float mnA = fmaxf(mA, tmA), mnB = fmaxf(mB, tmB);
        float alA = __expf(mA - mnA), alB = __expf(mB - mnB);
        mA = mnA; mB = mnB;

        uint32_t pA[8], pB[8];
        float sumA = 0.f, sumB = 0.f;
#pragma unroll
        for (int nt = 0; nt < 8; nt++) {
            float p0 = __expf(s[nt][0] - mnA);
            float p1 = __expf(s[nt][1] - mnA);
            float p2 = __expf(s[nt][2] - mnB);
            float p3 = __expf(s[nt][3] - mnB);
            sumA += p0 + p1;
            sumB += p2 + p3;
            pA[nt] = packh2(p0, p1);
            pB[nt] = packh2(p2, p3);
        }
        sumA += __shfl_xor_sync(0xffffffffu, sumA, 1);
        sumA += __shfl_xor_sync(0xffffffffu, sumA, 2);
        sumB += __shfl_xor_sync(0xffffffffu, sumB, 1);
        sumB += __shfl_xor_sync(0xffffffffu, sumB, 2);
        lA = lA * alA + sumA;
        lB = lB * alB + sumB;

#pragma unroll
        for (int jj = 0; jj < 16; jj++) {
            o[jj][0] *= alA; o[jj][1] *= alA;
            o[jj][2] *= alB; o[jj][3] *= alB;
        }

#pragma unroll
        for (int i = 0; i < 4; i++) {
            uint32_t a[4] = { pA[2 * i], pB[2 * i], pA[2 * i + 1], pB[2 * i + 1] };
#pragma unroll
            for (int nb = 0; nb < 8; nb++) {
                int n0 = nb * 16;
                uint32_t r0, r1, r2, r3;
                ldsm4t(r0, r1, r2, r3,
                       smaddr(Vst + (i * 16 + ((lane >> 3) & 1) * 8 + (lane & 7)) * 136 + n0 + (lane >> 4) * 8));
                uint32_t b0[2] = { r0, r1 }, b1[2] = { r2, r3 };
                mma16(o[nb * 2], a, b0);
                mma16(o[nb * 2 + 1], a, b1);
            }
        }
        __syncthreads();
    }

    const float invA = 1.f / lA;
    const float invB = 1.f / lB;
    __half* dA = g_O16 + ((size_t)(b * Nn) + q0 + rA) * Dd + h * HDd;
    __half* dB = g_O16 + ((size_t)(b * Nn) + q0 + rB) * Dd + h * HDd;
#pragma unroll
    for (int jj = 0; jj < 16; jj++) {
        int c0 = jj * 8 + 2 * tg;
        *(half2*)(dA + c0) = __floats2half2_rn(o[jj][0] * invA, o[jj][1] * invA);
        *(half2*)(dB + c0) = __floats2half2_rn(o[jj][2] * invB, o[jj][3] * invB);
    }
}

// ============================================================
// Kernel 3: out = O16 @ Wfc16 + bfc (fp32 out)
// grid (128 m-tiles, 8 n-tiles), block 256
// ============================================================
__global__ __launch_bounds__(256, 2) void fc_gemm(
    const float* __restrict__ bfc, float* __restrict__ out)
{
    extern __shared__ __half sm[];
    __half* As = sm;
    __half* Bs = sm + 3*A_ST;

    const int m0 = blockIdx.x * 128;
    const int n0 = blockIdx.y * 128;
    const int t    = threadIdx.x;
    const int lane = t & 31;
    const int warp = t >> 5;
    const int g    = lane >> 2;
    const int tg   = lane & 3;
    const int wm   = warp >> 1;
    const int wn   = warp & 1;

    float acc[2][8][4];
#pragma unroll
    for (int mt = 0; mt < 2; mt++)
#pragma unroll
        for (int nt = 0; nt < 8; nt++)
#pragma unroll
            for (int i = 0; i < 4; i++) acc[mt][nt][i] = 0.f;

    auto load_stage = [&](int k0, int st) {
        __half* Ad = As + st * A_ST;
        __half* Bd = Bs + st * B_ST;
#pragma unroll
        for (int pp = 0; pp < 4; pp++) {
            int idx = t + pp * 256;
            int r = idx >> 3, c = (idx & 7) * 8;
            CP16(smaddr(Ad + r * 72 + c), g_O16 + (size_t)(m0 + r) * Dd + k0 + c);
        }
#pragma unroll
        for (int pp = 0; pp < 4; pp++) {
            int idx = t + pp * 256;
            int r = idx >> 4, c = (idx & 15) * 8;
            CP16(smaddr(Bd + r * 136 + c), g_Wfc16 + (size_t)(k0 + r) * Dd + n0 + c);
        }
        CP_COMMIT();
    };

    GEMM_MAINLOOP()

#pragma unroll
    for (int mt = 0; mt < 2; mt++) {
#pragma unroll
        for (int half = 0; half < 2; half++) {
            int r = m0 + wm * 32 + mt * 16 + g + half * 8;
            float* dst = out + (size_t)r * Dd + n0;
#pragma unroll
            for (int nt = 0; nt < 8; nt++) {
                int cc = wn * 64 + nt * 8 + 2 * tg;
                float2 v;
                v.x = acc[mt][nt][half * 2 + 0] + bfc[n0 + cc];
                v.y = acc[mt][nt][half * 2 + 1] + bfc[n0 + cc + 1];
                *(float2*)(dst + cc) = v;
            }
        }
    }
}

// ============================================================
extern "C" void kernel_launch(void* const* d_in, const int* in_sizes, int n_in,
                              void* d_out, int out_size)
{
    const float* x      = (const float*)d_in[0];
    const int*   x_mask = (const int*)  d_in[1];
    const float* Wq     = (const float*)d_in[2];
    const float* bq     = (const float*)d_in[3];
    const float* Wk     = (const float*)d_in[4];
    const float* bk     = (const float*)d_in[5];
    const float* Wv     = (const float*)d_in[6];
    const float* bv     = (const float*)d_in[7];
    const float* Wfc    = (const float*)d_in[8];
    const float* bfc    = (const float*)d_in[9];
    float* out = (float*)d_out;

    static bool attr_done = false;
    if (!attr_done) {
        cudaFuncSetAttribute(attn_kernel, cudaFuncAttributeMaxDynamicSharedMemorySize, ATTN_SMEM_BYTES);
        cudaFuncSetAttribute(qkv_gemm,    cudaFuncAttributeMaxDynamicSharedMemorySize, GEMM_SMEM);
        cudaFuncSetAttribute(fc_gemm,     cudaFuncAttributeMaxDynamicSharedMemorySize, GEMM_SMEM);
        attr_done = true;
    }

    convert_all<<<2048, 256>>>(x, Wq, Wk, Wv, Wfc);
    qkv_gemm<<<dim3(128, 1, 24), 256, GEMM_SMEM>>>(bq, bk, bv);
    attn_kernel<<<dim3(8, 8, 16), 256, ATTN_SMEM_BYTES>>>(x_mask);
    fc_gemm<<<dim3(128, 8, 1), 256, GEMM_SMEM>>>(bfc, out);
}

// round 8
// speedup vs baseline: 1.0801x; 1.0801x over previous
#include <cuda_runtime.h>
#include <cuda_fp16.h>
#include <cstdint>
#include <math.h>

#define Bb 16
#define Nn 1024
#define Dd 1024
#define Hh 8
#define HDd 128
#define SCALE_F 0.08838834764831845f   // 1/sqrt(128)
#define NEG_F  -1e30f

// ---------------- scratch (static; no allocation allowed) ----------------
__device__ __align__(16) __half g_x16 [Bb*Nn*Dd];     // fp16 copy of x
__device__ __align__(16) __half g_Wq16[Hh*Dd*HDd];
__device__ __align__(16) __half g_Wk16[Hh*Dd*HDd];
__device__ __align__(16) __half g_Wv16[Hh*Dd*HDd];
__device__ __align__(16) __half g_Wfc16[Dd*Dd];
__device__ __align__(16) __half g_Q[Bb*Hh*Nn*HDd];    // [B,H,N,HD]
__device__ __align__(16) __half g_K[Bb*Hh*Nn*HDd];
__device__ __align__(16) __half g_V[Bb*Hh*Nn*HDd];
__device__ __align__(16) __half g_O16[Bb*Nn*Dd];      // [B,N,D]

// ---------------- helpers ----------------
__device__ __forceinline__ uint32_t smaddr(const void* p) {
    return (uint32_t)__cvta_generic_to_shared(p);
}
__device__ __forceinline__ void ldsm4(uint32_t& r0, uint32_t& r1, uint32_t& r2, uint32_t& r3, uint32_t a) {
    asm volatile("ldmatrix.sync.aligned.m8n8.x4.shared.b16 {%0,%1,%2,%3}, [%4];"
                 : "=r"(r0), "=r"(r1), "=r"(r2), "=r"(r3) : "r"(a));
}
__device__ __forceinline__ void ldsm4t(uint32_t& r0, uint32_t& r1, uint32_t& r2, uint32_t& r3, uint32_t a) {
    asm volatile("ldmatrix.sync.aligned.m8n8.x4.trans.shared.b16 {%0,%1,%2,%3}, [%4];"
                 : "=r"(r0), "=r"(r1), "=r"(r2), "=r"(r3) : "r"(a));
}
__device__ __forceinline__ void mma16(float c[4], const uint32_t a[4], const uint32_t b[2]) {
    asm volatile(
        "mma.sync.aligned.m16n8k16.row.col.f32.f16.f16.f32 "
        "{%0,%1,%2,%3}, {%4,%5,%6,%7}, {%8,%9}, {%0,%1,%2,%3};"
        : "+f"(c[0]), "+f"(c[1]), "+f"(c[2]), "+f"(c[3])
        : "r"(a[0]), "r"(a[1]), "r"(a[2]), "r"(a[3]), "r"(b[0]), "r"(b[1]));
}
__device__ __forceinline__ uint32_t packh2(float a, float b) {
    __half2 h = __floats2half2_rn(a, b);
    return *(uint32_t*)&h;
}

#define CP16(dst_sm, src_g) \
    asm volatile("cp.async.cg.shared.global [%0], [%1], 16;" :: "r"(dst_sm), "l"(src_g))
#define CP_COMMIT() asm volatile("cp.async.commit_group;")
#define CP_WAIT0()  asm volatile("cp.async.wait_group 0;")
#define CP_WAIT1()  asm volatile("cp.async.wait_group 1;")

// ============================================================
// Kernel 0: convert fp32 inputs to fp16 scratch
// ============================================================
#define CV_X  4194304           // float4 counts
#define CV_W  262144
__global__ __launch_bounds__(256) void convert_all(
    const float* __restrict__ x,  const float* __restrict__ Wq,
    const float* __restrict__ Wk, const float* __restrict__ Wv,
    const float* __restrict__ Wfc)
{
    const int total = CV_X + 4*CV_W;
    for (int i = blockIdx.x * blockDim.x + threadIdx.x; i < total; i += gridDim.x * blockDim.x) {
        const float* src; __half* dst; int off;
        if (i < CV_X)                 { src = x;   dst = g_x16;  off = i; }
        else if (i < CV_X + CV_W)     { src = Wq;  dst = g_Wq16; off = i - CV_X; }
        else if (i < CV_X + 2*CV_W)   { src = Wk;  dst = g_Wk16; off = i - CV_X - CV_W; }
        else if (i < CV_X + 3*CV_W)   { src = Wv;  dst = g_Wv16; off = i - CV_X - 2*CV_W; }
        else                          { src = Wfc; dst = g_Wfc16; off = i - CV_X - 3*CV_W; }
        float4 v = ((const float4*)src)[off];
        uint2 u;
        u.x = packh2(v.x, v.y);
        u.y = packh2(v.z, v.w);
        ((uint2*)dst)[off] = u;
    }
}

// ============================================================
// GEMM smem geometry (shared by qkv & fc): 2-stage, k-depth 64
// ============================================================
#define A_ST 9216     // 128 * 72 halves
#define B_ST 8704     // 64 * 136 halves
#define GEMM_SMEM ((2*(A_ST + B_ST)) * 2)

// ============================================================
// Kernel 1: fused QKV projection (fp16 in, fp16 out)
// grid (128 m-tiles, 1, 24 = proj*8+head), block 256
// ============================================================
__global__ __launch_bounds__(256) void qkv_gemm(
    const float* __restrict__ bq, const float* __restrict__ bk, const float* __restrict__ bv)
{
    extern __shared__ __half sm[];
    __half* As = sm;                // [2][128][72]
    __half* Bs = sm + 2*A_ST;       // [2][64][136]

    const int z = blockIdx.z;
    const int p = z >> 3;
    const int h = z & 7;
    const __half* W   = (p == 0 ? g_Wq16 : (p == 1 ? g_Wk16 : g_Wv16)) + (size_t)h * Dd * HDd;
    const float* bias = (p == 0 ? bq : (p == 1 ? bk : bv)) + h * HDd;
    __half* Cout      = (p == 0 ? g_Q : (p == 1 ? g_K : g_V));

    const int m0   = blockIdx.x * 128;
    const int t    = threadIdx.x;
    const int lane = t & 31;
    const int warp = t >> 5;
    const int g    = lane >> 2;
    const int tg   = lane & 3;
    const int wm   = warp >> 1;
    const int wn   = warp & 1;

    float acc[2][8][4];
#pragma unroll
    for (int mt = 0; mt < 2; mt++)
#pragma unroll
        for (int nt = 0; nt < 8; nt++)
#pragma unroll
            for (int i = 0; i < 4; i++) acc[mt][nt][i] = 0.f;

    auto load_stage = [&](int k0, int st) {
        __half* Ad = As + st * A_ST;
        __half* Bd = Bs + st * B_ST;
#pragma unroll
        for (int pp = 0; pp < 4; pp++) {
            int idx = t + pp * 256;
            int r = idx >> 3, c = (idx & 7) * 8;
            CP16(smaddr(Ad + r * 72 + c), g_x16 + (size_t)(m0 + r) * Dd + k0 + c);
        }
#pragma unroll
        for (int pp = 0; pp < 4; pp++) {
            int idx = t + pp * 256;
            int r = idx >> 4, c = (idx & 15) * 8;
            CP16(smaddr(Bd + r * 136 + c), W + (size_t)(k0 + r) * HDd + c);
        }
    };

    load_stage(0, 0);
    CP_COMMIT();

    for (int s = 0; s < 16; s++) {
        int cur = s & 1;
        if (s < 15) { load_stage((s + 1) * 64, cur ^ 1); CP_COMMIT(); CP_WAIT1(); }
        else        { CP_WAIT0(); }
        __syncthreads();

        const __half* Ac = As + cur * A_ST;
        const __half* Bc = Bs + cur * B_ST;
#pragma unroll
        for (int ks = 0; ks < 4; ks++) {
            int kk = ks * 16;
            uint32_t a[2][4];
#pragma unroll
            for (int mt = 0; mt < 2; mt++)
                ldsm4(a[mt][0], a[mt][1], a[mt][2], a[mt][3],
                      smaddr(Ac + (wm * 32 + mt * 16 + (lane & 15)) * 72 + kk + ((lane >> 4) << 3)));
            uint32_t bf[8][2];
#pragma unroll
            for (int nb = 0; nb < 4; nb++) {
                int n0 = wn * 64 + nb * 16;
                uint32_t r0, r1, r2, r3;
                ldsm4t(r0, r1, r2, r3,
                       smaddr(Bc + (kk + ((lane >> 3) & 1) * 8 + (lane & 7)) * 136 + n0 + (lane >> 4) * 8));
                bf[nb * 2][0] = r0; bf[nb * 2][1] = r1;
                bf[nb * 2 + 1][0] = r2; bf[nb * 2 + 1][1] = r3;
            }
#pragma unroll
            for (int mt = 0; mt < 2; mt++)
#pragma unroll
                for (int nt = 0; nt < 8; nt++)
                    mma16(acc[mt][nt], a[mt], bf[nt]);
        }
        __syncthreads();
    }

    // epilogue -> [B,H,N,HD] fp16 (+bias)
#pragma unroll
    for (int mt = 0; mt < 2; mt++) {
#pragma unroll
        for (int half = 0; half < 2; half++) {
            int r  = m0 + wm * 32 + mt * 16 + g + half * 8;
            int bb = r >> 10;
            int n  = r & 1023;
            __half* dst = Cout + (((size_t)(bb * Hh + h)) * Nn + n) * HDd;
#pragma unroll
            for (int nt = 0; nt < 8; nt++) {
                int cc = wn * 64 + nt * 8 + 2 * tg;
                *(half2*)(dst + cc) = __floats2half2_rn(
                    acc[mt][nt][half * 2 + 0] + bias[cc],
                    acc[mt][nt][half * 2 + 1] + bias[cc + 1]);
            }
        }
    }
}

// ============================================================
// Kernel 2: flash attention, warp-private softmax, P in regs
// grid (8 q-tiles, 8 heads, 16 batch), block 256 (8 warps x 16 rows)
// launch_bounds(256,2): force 2 CTAs/SM so softmax phases of one CTA
// overlap MMA phases of the other (smem 2x104.5KB fits 228KB).
// ============================================================
#define Q_SZ  17408            // 128*136 halves
#define KV_ST 8704             // 64*136 halves
#define ATTN_SMEM_BYTES ((Q_SZ + 4*KV_ST)*2 + 2*64*4)

__global__ __launch_bounds__(256, 2) void attn_kernel(const int* __restrict__ x_mask)
{
    extern __shared__ __half sm[];
    __half* Qs = sm;                    // [128][136]
    __half* Ks = sm + Q_SZ;             // [2][64][136]
    __half* Vs = Ks + 2 * KV_ST;        // [2][64][136]
    int*    km = (int*)(Vs + 2 * KV_ST);// [2][64]

    const int qt = blockIdx.x, h = blockIdx.y, b = blockIdx.z;
    const int t    = threadIdx.x;
    const int lane = t & 31;
    const int warp = t >> 5;
    const int g    = lane >> 2;
    const int tg   = lane & 3;
    const size_t bh = ((size_t)b * Hh + h) * Nn;
    const int q0 = qt * 128;
    const int rA = warp * 16 + g;
    const int rB = rA + 8;

#pragma unroll
    for (int pp = 0; pp < 8; pp++) {
        int idx = t + pp * 256;
        int r = idx >> 4, c = (idx & 15) * 8;
        CP16(smaddr(Qs + r * 136 + c), g_Q + (bh + q0 + r) * HDd + c);
    }
    auto load_kv = [&](int kt, int st) {
        int k0 = kt * 64;
        __half* Kd = Ks + st * KV_ST;
        __half* Vd = Vs + st * KV_ST;
#pragma unroll
        for (int pp = 0; pp < 4; pp++) {
            int idx = t + pp * 256;
            int r = idx >> 4, c = (idx & 15) * 8;
            CP16(smaddr(Kd + r * 136 + c), g_K + (bh + k0 + r) * HDd + c);
            CP16(smaddr(Vd + r * 136 + c), g_V + (bh + k0 + r) * HDd + c);
        }
        if (t < 64) km[st * 64 + t] = x_mask[b * Nn + k0 + t];
    };
    load_kv(0, 0);
    CP_COMMIT();

    const int qmA = x_mask[b * Nn + q0 + rA];
    const int qmB = x_mask[b * Nn + q0 + rB];
    float mA = -INFINITY, mB = -INFINITY, lA = 0.f, lB = 0.f;

    float o[16][4];
#pragma unroll
    for (int jj = 0; jj < 16; jj++)
#pragma unroll
        for (int i = 0; i < 4; i++) o[jj][i] = 0.f;

    for (int kt = 0; kt < 16; kt++) {
        const int cur = kt & 1;
        if (kt < 15) { load_kv(kt + 1, cur ^ 1); CP_COMMIT(); CP_WAIT1(); }
        else         { CP_WAIT0(); }
        __syncthreads();

        const __half* Kst = Ks + cur * KV_ST;
        const __half* Vst = Vs + cur * KV_ST;
        const int*    kmc = km + cur * 64;

        float s[8][4];
#pragma unroll
        for (int nt = 0; nt < 8; nt++)
#pragma unroll
            for (int i = 0; i < 4; i++) s[nt][i] = 0.f;

#pragma unroll
        for (int ks = 0; ks < 8; ks++) {
            int kk = ks * 16;
            uint32_t a[4];
            ldsm4(a[0], a[1], a[2], a[3],
                  smaddr(Qs + (warp * 16 + (lane & 15)) * 136 + kk + ((lane >> 4) << 3)));
#pragma unroll
            for (int nb = 0; nb < 4; nb++) {
                int n0 = nb * 16;
                uint32_t r0, r1, r2, r3;
                ldsm4(r0, r1, r2, r3,
                      smaddr(Kst + (n0 + ((lane >> 4) << 3) + (lane & 7)) * 136 + kk + ((lane >> 3) & 1) * 8));
                uint32_t b0[2] = { r0, r1 }, b1[2] = { r2, r3 };
                mma16(s[nb * 2], a, b0);
                mma16(s[nb * 2 + 1], a, b1);
            }
        }

#pragma unroll
        for (int nt = 0; nt < 8; nt++) {
            int c0 = nt * 8 + 2 * tg;
            int k0m = kmc[c0], k1m = kmc[c0 + 1];
            s[nt][0] = (qmA & k0m) ? s[nt][0] * SCALE_F : NEG_F;
            s[nt][1] = (qmA & k1m) ? s[nt][1] * SCALE_F : NEG_F;
            s[nt][2] = (qmB & k0m) ? s[nt][2] * SCALE_F : NEG_F;
            s[nt][3] = (qmB & k1m) ? s[nt][3] * SCALE_F : NEG_F;
        }

        float tmA = s[0][0], tmB = s[0][2];
#pragma unroll
        for (int nt = 0; nt < 8; nt++) {
            tmA = fmaxf(tmA, fmaxf(s[nt][0], s[nt][1]));
            tmB = fmaxf(tmB, fmaxf(s[nt][2], s[nt][3]));
        }
        tmA = fmaxf(tmA, __shfl_xor_sync(0xffffffffu, tmA, 1));
        tmA = fmaxf(tmA, __shfl_xor_sync(0xffffffffu, tmA, 2));
        tmB = fmaxf(tmB, __shfl_xor_sync(0xffffffffu, tmB, 1));
        tmB = fmaxf(tmB, __shfl_xor_sync(0xffffffffu, tmB, 2));

        float mnA = fmaxf(mA, tmA), mnB = fmaxf(mB, tmB);
        float alA = __expf(mA - mnA), alB = __expf(mB - mnB);
        mA = mnA; mB = mnB;

        uint32_t pA[8], pB[8];
        float sumA = 0.f, sumB = 0.f;
#pragma unroll
        for (int nt = 0; nt < 8; nt++) {
            float p0 = __expf(s[nt][0] - mnA);
            float p1 = __expf(s[nt][1] - mnA);
            float p2 = __expf(s[nt][2] - mnB);
            float p3 = __expf(s[nt][3] - mnB);
            sumA += p0 + p1;
            sumB += p2 + p3;
            pA[nt] = packh2(p0, p1);
            pB[nt] = packh2(p2, p3);
        }
        sumA += __shfl_xor_sync(0xffffffffu, sumA, 1);
        sumA += __shfl_xor_sync(0xffffffffu, sumA, 2);
        sumB += __shfl_xor_sync(0xffffffffu, sumB, 1);
        sumB += __shfl_xor_sync(0xffffffffu, sumB, 2);
        lA = lA * alA + sumA;
        lB = lB * alB + sumB;

#pragma unroll
        for (int jj = 0; jj < 16; jj++) {
            o[jj][0] *= alA; o[jj][1] *= alA;
            o[jj][2] *= alB; o[jj][3] *= alB;
        }

#pragma unroll
        for (int i = 0; i < 4; i++) {
            uint32_t a[4] = { pA[2 * i], pB[2 * i], pA[2 * i + 1], pB[2 * i + 1] };
#pragma unroll
            for (int nb = 0; nb < 8; nb++) {
                int n0 = nb * 16;
                uint32_t r0, r1, r2, r3;
                ldsm4t(r0, r1, r2, r3,
                       smaddr(Vst + (i * 16 + ((lane >> 3) & 1) * 8 + (lane & 7)) * 136 + n0 + (lane >> 4) * 8));
                uint32_t b0[2] = { r0, r1 }, b1[2] = { r2, r3 };
                mma16(o[nb * 2], a, b0);
                mma16(o[nb * 2 + 1], a, b1);
            }
        }
        __syncthreads();
    }

    const float invA = 1.f / lA;
    const float invB = 1.f / lB;
    __half* dA = g_O16 + ((size_t)(b * Nn) + q0 + rA) * Dd + h * HDd;
    __half* dB = g_O16 + ((size_t)(b * Nn) + q0 + rB) * Dd + h * HDd;
#pragma unroll
    for (int jj = 0; jj < 16; jj++) {
        int c0 = jj * 8 + 2 * tg;
        *(half2*)(dA + c0) = __floats2half2_rn(o[jj][0] * invA, o[jj][1] * invA);
        *(half2*)(dB + c0) = __floats2half2_rn(o[jj][2] * invB, o[jj][3] * invB);
    }
}

// ============================================================
// Kernel 3: out = O16 @ Wfc16 + bfc (fp32 out)
// grid (128 m-tiles, 8 n-tiles), block 256
// ============================================================
__global__ __launch_bounds__(256) void fc_gemm(
    const float* __restrict__ bfc, float* __restrict__ out)
{
    extern __shared__ __half sm[];
    __half* As = sm;
    __half* Bs = sm + 2*A_ST;

    const int m0 = blockIdx.x * 128;
    const int n0 = blockIdx.y * 128;
    const int t    = threadIdx.x;
    const int lane = t & 31;
    const int warp = t >> 5;
    const int g    = lane >> 2;
    const int tg   = lane & 3;
    const int wm   = warp >> 1;
    const int wn   = warp & 1;

    float acc[2][8][4];
#pragma unroll
    for (int mt = 0; mt < 2; mt++)
#pragma unroll
        for (int nt = 0; nt < 8; nt++)
#pragma unroll
            for (int i = 0; i < 4; i++) acc[mt][nt][i] = 0.f;

    auto load_stage = [&](int k0, int st) {
        __half* Ad = As + st * A_ST;
        __half* Bd = Bs + st * B_ST;
#pragma unroll
        for (int pp = 0; pp < 4; pp++) {
            int idx = t + pp * 256;
            int r = idx >> 3, c = (idx & 7) * 8;
            CP16(smaddr(Ad + r * 72 + c), g_O16 + (size_t)(m0 + r) * Dd + k0 + c);
        }
#pragma unroll
        for (int pp = 0; pp < 4; pp++) {
            int idx = t + pp * 256;
            int r = idx >> 4, c = (idx & 15) * 8;
            CP16(smaddr(Bd + r * 136 + c), g_Wfc16 + (size_t)(k0 + r) * Dd + n0 + c);
        }
    };

    load_stage(0, 0);
    CP_COMMIT();

    for (int s = 0; s < 16; s++) {
        int cur = s & 1;
        if (s < 15) { load_stage((s + 1) * 64, cur ^ 1); CP_COMMIT(); CP_WAIT1(); }
        else        { CP_WAIT0(); }
        __syncthreads();

        const __half* Ac = As + cur * A_ST;
        const __half* Bc = Bs + cur * B_ST;
#pragma unroll
        for (int ks = 0; ks < 4; ks++) {
            int kk = ks * 16;
            uint32_t a[2][4];
#pragma unroll
            for (int mt = 0; mt < 2; mt++)
                ldsm4(a[mt][0], a[mt][1], a[mt][2], a[mt][3],
                      smaddr(Ac + (wm * 32 + mt * 16 + (lane & 15)) * 72 + kk + ((lane >> 4) << 3)));
            uint32_t bf[8][2];
#pragma unroll
            for (int nb = 0; nb < 4; nb++) {
                int nn0 = wn * 64 + nb * 16;
                uint32_t r0, r1, r2, r3;
                ldsm4t(r0, r1, r2, r3,
                       smaddr(Bc + (kk + ((lane >> 3) & 1) * 8 + (lane & 7)) * 136 + nn0 + (lane >> 4) * 8));
                bf[nb * 2][0] = r0; bf[nb * 2][1] = r1;
                bf[nb * 2 + 1][0] = r2; bf[nb * 2 + 1][1] = r3;
            }
#pragma unroll
            for (int mt = 0; mt < 2; mt++)
#pragma unroll
                for (int nt = 0; nt < 8; nt++)
                    mma16(acc[mt][nt], a[mt], bf[nt]);
        }
        __syncthreads();
    }

#pragma unroll
    for (int mt = 0; mt < 2; mt++) {
#pragma unroll
        for (int half = 0; half < 2; half++) {
            int r = m0 + wm * 32 + mt * 16 + g + half * 8;
            float* dst = out + (size_t)r * Dd + n0;
#pragma unroll
            for (int nt = 0; nt < 8; nt++) {
                int cc = wn * 64 + nt * 8 + 2 * tg;
                float2 v;
                v.x = acc[mt][nt][half * 2 + 0] + bfc[n0 + cc];
                v.y = acc[mt][nt][half * 2 + 1] + bfc[n0 + cc + 1];
                *(float2*)(dst + cc) = v;
            }
        }
    }
}

// ============================================================
extern "C" void kernel_launch(void* const* d_in, const int* in_sizes, int n_in,
                              void* d_out, int out_size)
{
    const float* x      = (const float*)d_in[0];
    const int*   x_mask = (const int*)  d_in[1];
    const float* Wq     = (const float*)d_in[2];
    const float* bq     = (const float*)d_in[3];
    const float* Wk     = (const float*)d_in[4];
    const float* bk     = (const float*)d_in[5];
    const float* Wv     = (const float*)d_in[6];
    const float* bv     = (const float*)d_in[7];
    const float* Wfc    = (const float*)d_in[8];
    const float* bfc    = (const float*)d_in[9];
    float* out = (float*)d_out;

    static bool attr_done = false;
    if (!attr_done) {
        cudaFuncSetAttribute(attn_kernel, cudaFuncAttributeMaxDynamicSharedMemorySize, ATTN_SMEM_BYTES);
        cudaFuncSetAttribute(qkv_gemm,    cudaFuncAttributeMaxDynamicSharedMemorySize, GEMM_SMEM);
        cudaFuncSetAttribute(fc_gemm,     cudaFuncAttributeMaxDynamicSharedMemorySize, GEMM_SMEM);
        attr_done = true;
    }

    convert_all<<<2048, 256>>>(x, Wq, Wk, Wv, Wfc);
    qkv_gemm<<<dim3(128, 1, 24), 256, GEMM_SMEM>>>(bq, bk, bv);
    attn_kernel<<<dim3(8, 8, 16), 256, ATTN_SMEM_BYTES>>>(x_mask);
    fc_gemm<<<dim3(128, 8, 1), 256, GEMM_SMEM>>>(bfc, out);
}

// round 9
// speedup vs baseline: 1.1021x; 1.0204x over previous
#include <cuda_runtime.h>
#include <cuda_fp16.h>
#include <cstdint>
#include <math.h>

#define Bb 16
#define Nn 1024
#define Dd 1024
#define Hh 8
#define HDd 128
#define SCALE_F 0.08838834764831845f   // 1/sqrt(128)
// scale folded with log2(e): softmax computed in exp2 domain
#define SCALE2  (0.08838834764831845f * 1.4426950408889634f)
#define NEG_F  -1e30f

// ---------------- scratch (static; no allocation allowed) ----------------
__device__ __align__(16) __half g_x16 [Bb*Nn*Dd];     // fp16 copy of x
__device__ __align__(16) __half g_Wq16[Hh*Dd*HDd];
__device__ __align__(16) __half g_Wk16[Hh*Dd*HDd];
__device__ __align__(16) __half g_Wv16[Hh*Dd*HDd];
__device__ __align__(16) __half g_Wfc16[Dd*Dd];
__device__ __align__(16) __half g_Q[Bb*Hh*Nn*HDd];    // [B,H,N,HD]
__device__ __align__(16) __half g_K[Bb*Hh*Nn*HDd];
__device__ __align__(16) __half g_V[Bb*Hh*Nn*HDd];
__device__ __align__(16) __half g_O16[Bb*Nn*Dd];      // [B,N,D]

// ---------------- helpers ----------------
__device__ __forceinline__ uint32_t smaddr(const void* p) {
    return (uint32_t)__cvta_generic_to_shared(p);
}
__device__ __forceinline__ void ldsm4(uint32_t& r0, uint32_t& r1, uint32_t& r2, uint32_t& r3, uint32_t a) {
    asm volatile("ldmatrix.sync.aligned.m8n8.x4.shared.b16 {%0,%1,%2,%3}, [%4];"
                 : "=r"(r0), "=r"(r1), "=r"(r2), "=r"(r3) : "r"(a));
}
__device__ __forceinline__ void ldsm4t(uint32_t& r0, uint32_t& r1, uint32_t& r2, uint32_t& r3, uint32_t a) {
    asm volatile("ldmatrix.sync.aligned.m8n8.x4.trans.shared.b16 {%0,%1,%2,%3}, [%4];"
                 : "=r"(r0), "=r"(r1), "=r"(r2), "=r"(r3) : "r"(a));
}
__device__ __forceinline__ void mma16(float c[4], const uint32_t a[4], const uint32_t b[2]) {
    asm volatile(
        "mma.sync.aligned.m16n8k16.row.col.f32.f16.f16.f32 "
        "{%0,%1,%2,%3}, {%4,%5,%6,%7}, {%8,%9}, {%0,%1,%2,%3};"
        : "+f"(c[0]), "+f"(c[1]), "+f"(c[2]), "+f"(c[3])
        : "r"(a[0]), "r"(a[1]), "r"(a[2]), "r"(a[3]), "r"(b[0]), "r"(b[1]));
}
__device__ __forceinline__ uint32_t packh2(float a, float b) {
    __half2 h = __floats2half2_rn(a, b);
    return *(uint32_t*)&h;
}
__device__ __forceinline__ uint32_t ex2h2(uint32_t x) {      // 2x fp16 exp2 in one MUFU
    uint32_t r;
    asm("ex2.approx.f16x2 %0, %1;" : "=r"(r) : "r"(x));
    return r;
}
__device__ __forceinline__ float ex2f(float x) {
    float r;
    asm("ex2.approx.f32 %0, %1;" : "=f"(r) : "f"(x));
    return r;
}

#define CP16(dst_sm, src_g) \
    asm volatile("cp.async.cg.shared.global [%0], [%1], 16;" :: "r"(dst_sm), "l"(src_g))
#define CP_COMMIT() asm volatile("cp.async.commit_group;")
#define CP_WAIT0()  asm volatile("cp.async.wait_group 0;")
#define CP_WAIT1()  asm volatile("cp.async.wait_group 1;")

// ============================================================
// Kernel 0: convert fp32 inputs to fp16 scratch
// ============================================================
#define CV_X  4194304           // float4 counts
#define CV_W  262144
__global__ __launch_bounds__(256) void convert_all(
    const float* __restrict__ x,  const float* __restrict__ Wq,
    const float* __restrict__ Wk, const float* __restrict__ Wv,
    const float* __restrict__ Wfc)
{
    const int total = CV_X + 4*CV_W;
    for (int i = blockIdx.x * blockDim.x + threadIdx.x; i < total; i += gridDim.x * blockDim.x) {
        const float* src; __half* dst; int off;
        if (i < CV_X)                 { src = x;   dst = g_x16;  off = i; }
        else if (i < CV_X + CV_W)     { src = Wq;  dst = g_Wq16; off = i - CV_X; }
        else if (i < CV_X + 2*CV_W)   { src = Wk;  dst = g_Wk16; off = i - CV_X - CV_W; }
        else if (i < CV_X + 3*CV_W)   { src = Wv;  dst = g_Wv16; off = i - CV_X - 2*CV_W; }
        else                          { src = Wfc; dst = g_Wfc16; off = i - CV_X - 3*CV_W; }
        float4 v = ((const float4*)src)[off];
        uint2 u;
        u.x = packh2(v.x, v.y);
        u.y = packh2(v.z, v.w);
        ((uint2*)dst)[off] = u;
    }
}

// ============================================================
// GEMM smem geometry (shared by qkv & fc): 2-stage, k-depth 64
// ============================================================
#define A_ST 9216     // 128 * 72 halves
#define B_ST 8704     // 64 * 136 halves
#define GEMM_SMEM ((2*(A_ST + B_ST)) * 2)

// ============================================================
// Kernel 1: fused QKV projection (fp16 in, fp16 out)
// grid (128 m-tiles, 1, 24 = proj*8+head), block 256
// ============================================================
__global__ __launch_bounds__(256) void qkv_gemm(
    const float* __restrict__ bq, const float* __restrict__ bk, const float* __restrict__ bv)
{
    extern __shared__ __half sm[];
    __half* As = sm;                // [2][128][72]
    __half* Bs = sm + 2*A_ST;       // [2][64][136]

    const int z = blockIdx.z;
    const int p = z >> 3;
    const int h = z & 7;
    const __half* W   = (p == 0 ? g_Wq16 : (p == 1 ? g_Wk16 : g_Wv16)) + (size_t)h * Dd * HDd;
    const float* bias = (p == 0 ? bq : (p == 1 ? bk : bv)) + h * HDd;
    __half* Cout      = (p == 0 ? g_Q : (p == 1 ? g_K : g_V));

    const int m0   = blockIdx.x * 128;
    const int t    = threadIdx.x;
    const int lane = t & 31;
    const int warp = t >> 5;
    const int g    = lane >> 2;
    const int tg   = lane & 3;
    const int wm   = warp >> 1;
    const int wn   = warp & 1;

    float acc[2][8][4];
#pragma unroll
    for (int mt = 0; mt < 2; mt++)
#pragma unroll
        for (int nt = 0; nt < 8; nt++)
#pragma unroll
            for (int i = 0; i < 4; i++) acc[mt][nt][i] = 0.f;

    auto load_stage = [&](int k0, int st) {
        __half* Ad = As + st * A_ST;
        __half* Bd = Bs + st * B_ST;
#pragma unroll
        for (int pp = 0; pp < 4; pp++) {
            int idx = t + pp * 256;
            int r = idx >> 3, c = (idx & 7) * 8;
            CP16(smaddr(Ad + r * 72 + c), g_x16 + (size_t)(m0 + r) * Dd + k0 + c);
        }
#pragma unroll
        for (int pp = 0; pp < 4; pp++) {
            int idx = t + pp * 256;
            int r = idx >> 4, c = (idx & 15) * 8;
            CP16(smaddr(Bd + r * 136 + c), W + (size_t)(k0 + r) * HDd + c);
        }
    };

    load_stage(0, 0);
    CP_COMMIT();

    for (int s = 0; s < 16; s++) {
        int cur = s & 1;
        if (s < 15) { load_stage((s + 1) * 64, cur ^ 1); CP_COMMIT(); CP_WAIT1(); }
        else        { CP_WAIT0(); }
        __syncthreads();

        const __half* Ac = As + cur * A_ST;
        const __half* Bc = Bs + cur * B_ST;
#pragma unroll
        for (int ks = 0; ks < 4; ks++) {
            int kk = ks * 16;
            uint32_t a[2][4];
#pragma unroll
            for (int mt = 0; mt < 2; mt++)
                ldsm4(a[mt][0], a[mt][1], a[mt][2], a[mt][3],
                      smaddr(Ac + (wm * 32 + mt * 16 + (lane & 15)) * 72 + kk + ((lane >> 4) << 3)));
            uint32_t bf[8][2];
#pragma unroll
            for (int nb = 0; nb < 4; nb++) {
                int n0 = wn * 64 + nb * 16;
                uint32_t r0, r1, r2, r3;
                ldsm4t(r0, r1, r2, r3,
                       smaddr(Bc + (kk + ((lane >> 3) & 1) * 8 + (lane & 7)) * 136 + n0 + (lane >> 4) * 8));
                bf[nb * 2][0] = r0; bf[nb * 2][1] = r1;
                bf[nb * 2 + 1][0] = r2; bf[nb * 2 + 1][1] = r3;
            }
#pragma unroll
            for (int mt = 0; mt < 2; mt++)
#pragma unroll
                for (int nt = 0; nt < 8; nt++)
                    mma16(acc[mt][nt], a[mt], bf[nt]);
        }
        __syncthreads();
    }

    // epilogue -> [B,H,N,HD] fp16 (+bias)
#pragma unroll
    for (int mt = 0; mt < 2; mt++) {
#pragma unroll
        for (int half = 0; half < 2; half++) {
            int r  = m0 + wm * 32 + mt * 16 + g + half * 8;
            int bb = r >> 10;
            int n  = r & 1023;
            __half* dst = Cout + (((size_t)(bb * Hh + h)) * Nn + n) * HDd;
#pragma unroll
            for (int nt = 0; nt < 8; nt++) {
                int cc = wn * 64 + nt * 8 + 2 * tg;
                *(half2*)(dst + cc) = __floats2half2_rn(
                    acc[mt][nt][half * 2 + 0] + bias[cc],
                    acc[mt][nt][half * 2 + 1] + bias[cc + 1]);
            }
        }
    }
}

// ============================================================
// Kernel 2: flash attention, warp-private softmax in exp2 domain,
// P via ex2.approx.f16x2 (half the MUFU ops of __expf).
// grid (8 q-tiles, 8 heads, 16 batch), block 256, 2 CTAs/SM
// ============================================================
#define Q_SZ  17408            // 128*136 halves
#define KV_ST 8704             // 64*136 halves
#define ATTN_SMEM_BYTES ((Q_SZ + 4*KV_ST)*2 + 2*64*4)

__global__ __launch_bounds__(256, 2) void attn_kernel(const int* __restrict__ x_mask)
{
    extern __shared__ __half sm[];
    __half* Qs = sm;                    // [128][136]
    __half* Ks = sm + Q_SZ;             // [2][64][136]
    __half* Vs = Ks + 2 * KV_ST;        // [2][64][136]
    int*    km = (int*)(Vs + 2 * KV_ST);// [2][64]

    const int qt = blockIdx.x, h = blockIdx.y, b = blockIdx.z;
    const int t    = threadIdx.x;
    const int lane = t & 31;
    const int warp = t >> 5;
    const int g    = lane >> 2;
    const int tg   = lane & 3;
    const size_t bh = ((size_t)b * Hh + h) * Nn;
    const int q0 = qt * 128;
    const int rA = warp * 16 + g;
    const int rB = rA + 8;

#pragma unroll
    for (int pp = 0; pp < 8; pp++) {
        int idx = t + pp * 256;
        int r = idx >> 4, c = (idx & 15) * 8;
        CP16(smaddr(Qs + r * 136 + c), g_Q + (bh + q0 + r) * HDd + c);
    }
    auto load_kv = [&](int kt, int st) {
        int k0 = kt * 64;
        __half* Kd = Ks + st * KV_ST;
        __half* Vd = Vs + st * KV_ST;
#pragma unroll
        for (int pp = 0; pp < 4; pp++) {
            int idx = t + pp * 256;
            int r = idx >> 4, c = (idx & 15) * 8;
            CP16(smaddr(Kd + r * 136 + c), g_K + (bh + k0 + r) * HDd + c);
            CP16(smaddr(Vd + r * 136 + c), g_V + (bh + k0 + r) * HDd + c);
        }
        if (t < 64) km[st * 64 + t] = x_mask[b * Nn + k0 + t];
    };
    load_kv(0, 0);
    CP_COMMIT();

    const int qmA = x_mask[b * Nn + q0 + rA];
    const int qmB = x_mask[b * Nn + q0 + rB];
    float mA = -INFINITY, mB = -INFINITY, lA = 0.f, lB = 0.f;

    float o[16][4];
#pragma unroll
    for (int jj = 0; jj < 16; jj++)
#pragma unroll
        for (int i = 0; i < 4; i++) o[jj][i] = 0.f;

    for (int kt = 0; kt < 16; kt++) {
        const int cur = kt & 1;
        if (kt < 15) { load_kv(kt + 1, cur ^ 1); CP_COMMIT(); CP_WAIT1(); }
        else         { CP_WAIT0(); }
        __syncthreads();

        const __half* Kst = Ks + cur * KV_ST;
        const __half* Vst = Vs + cur * KV_ST;
        const int*    kmc = km + cur * 64;

        float s[8][4];
#pragma unroll
        for (int nt = 0; nt < 8; nt++)
#pragma unroll
            for (int i = 0; i < 4; i++) s[nt][i] = 0.f;

#pragma unroll
        for (int ks = 0; ks < 8; ks++) {
            int kk = ks * 16;
            uint32_t a[4];
            ldsm4(a[0], a[1], a[2], a[3],
                  smaddr(Qs + (warp * 16 + (lane & 15)) * 136 + kk + ((lane >> 4) << 3)));
#pragma unroll
            for (int nb = 0; nb < 4; nb++) {
                int n0 = nb * 16;
                uint32_t r0, r1, r2, r3;
                ldsm4(r0, r1, r2, r3,
                      smaddr(Kst + (n0 + ((lane >> 4) << 3) + (lane & 7)) * 136 + kk + ((lane >> 3) & 1) * 8));
                uint32_t b0[2] = { r0, r1 }, b1[2] = { r2, r3 };
                mma16(s[nb * 2], a, b0);
                mma16(s[nb * 2 + 1], a, b1);
            }
        }

        // ---- mask + scale (log2 domain: s*scale*log2e; masked = -1e30) ----
#pragma unroll
        for (int nt = 0; nt < 8; nt++) {
            int c0 = nt * 8 + 2 * tg;
            int k0m = kmc[c0], k1m = kmc[c0 + 1];
            s[nt][0] = (qmA & k0m) ? s[nt][0] * SCALE2 : NEG_F;
            s[nt][1] = (qmA & k1m) ? s[nt][1] * SCALE2 : NEG_F;
            s[nt][2] = (qmB & k0m) ? s[nt][2] * SCALE2 : NEG_F;
            s[nt][3] = (qmB & k1m) ? s[nt][3] * SCALE2 : NEG_F;
        }

        float tmA = s[0][0], tmB = s[0][2];
#pragma unroll
        for (int nt = 0; nt < 8; nt++) {
            tmA = fmaxf(tmA, fmaxf(s[nt][0], s[nt][1]));
            tmB = fmaxf(tmB, fmaxf(s[nt][2], s[nt][3]));
        }
        tmA = fmaxf(tmA, __shfl_xor_sync(0xffffffffu, tmA, 1));
        tmA = fmaxf(tmA, __shfl_xor_sync(0xffffffffu, tmA, 2));
        tmB = fmaxf(tmB, __shfl_xor_sync(0xffffffffu, tmB, 1));
        tmB = fmaxf(tmB, __shfl_xor_sync(0xffffffffu, tmB, 2));

        float mnA = fmaxf(mA, tmA), mnB = fmaxf(mB, tmB);
        float alA = ex2f(mA - mnA), alB = ex2f(mB - mnB);
        mA = mnA; mB = mnB;

        // ---- P = exp2(s - m) via half2 MUFU; fp32 row sums ----
        uint32_t pA[8], pB[8];
        float sumA = 0.f, sumB = 0.f;
#pragma unroll
        for (int nt = 0; nt < 8; nt++) {
            uint32_t hA = packh2(s[nt][0] - mnA, s[nt][1] - mnA);
            uint32_t hB = packh2(s[nt][2] - mnB, s[nt][3] - mnB);
            uint32_t eA = ex2h2(hA);
            uint32_t eB = ex2h2(hB);
            pA[nt] = eA;
            pB[nt] = eB;
            float2 fA = __half22float2(*(half2*)&eA);
            float2 fB = __half22float2(*(half2*)&eB);
            sumA += fA.x + fA.y;
            sumB += fB.x + fB.y;
        }
        sumA += __shfl_xor_sync(0xffffffffu, sumA, 1);
        sumA += __shfl_xor_sync(0xffffffffu, sumA, 2);
        sumB += __shfl_xor_sync(0xffffffffu, sumB, 1);
        sumB += __shfl_xor_sync(0xffffffffu, sumB, 2);
        lA = lA * alA + sumA;
        lB = lB * alB + sumB;

#pragma unroll
        for (int jj = 0; jj < 16; jj++) {
            o[jj][0] *= alA; o[jj][1] *= alA;
            o[jj][2] *= alB; o[jj][3] *= alB;
        }

#pragma unroll
        for (int i = 0; i < 4; i++) {
            uint32_t a[4] = { pA[2 * i], pB[2 * i], pA[2 * i + 1], pB[2 * i + 1] };
#pragma unroll
            for (int nb = 0; nb < 8; nb++) {
                int n0 = nb * 16;
                uint32_t r0, r1, r2, r3;
                ldsm4t(r0, r1, r2, r3,
                       smaddr(Vst + (i * 16 + ((lane >> 3) & 1) * 8 + (lane & 7)) * 136 + n0 + (lane >> 4) * 8));
                uint32_t b0[2] = { r0, r1 }, b1[2] = { r2, r3 };
                mma16(o[nb * 2], a, b0);
                mma16(o[nb * 2 + 1], a, b1);
            }
        }
        __syncthreads();
    }

    const float invA = 1.f / lA;
    const float invB = 1.f / lB;
    __half* dA = g_O16 + ((size_t)(b * Nn) + q0 + rA) * Dd + h * HDd;
    __half* dB = g_O16 + ((size_t)(b * Nn) + q0 + rB) * Dd + h * HDd;
#pragma unroll
    for (int jj = 0; jj < 16; jj++) {
        int c0 = jj * 8 + 2 * tg;
        *(half2*)(dA + c0) = __floats2half2_rn(o[jj][0] * invA, o[jj][1] * invA);
        *(half2*)(dB + c0) = __floats2half2_rn(o[jj][2] * invB, o[jj][3] * invB);
    }
}

// ============================================================
// Kernel 3: out = O16 @ Wfc16 + bfc (fp32 out)
// grid (128 m-tiles, 8 n-tiles), block 256
// ============================================================
__global__ __launch_bounds__(256) void fc_gemm(
    const float* __restrict__ bfc, float* __restrict__ out)
{
    extern __shared__ __half sm[];
    __half* As = sm;
    __half* Bs = sm + 2*A_ST;

    const int m0 = blockIdx.x * 128;
    const int n0 = blockIdx.y * 128;
    const int t    = threadIdx.x;
    const int lane = t & 31;
    const int warp = t >> 5;
    const int g    = lane >> 2;
    const int tg   = lane & 3;
    const int wm   = warp >> 1;
    const int wn   = warp & 1;

    float acc[2][8][4];
#pragma unroll
    for (int mt = 0; mt < 2; mt++)
#pragma unroll
        for (int nt = 0; nt < 8; nt++)
#pragma unroll
            for (int i = 0; i < 4; i++) acc[mt][nt][i] = 0.f;

    auto load_stage = [&](int k0, int st) {
        __half* Ad = As + st * A_ST;
        __half* Bd = Bs + st * B_ST;
#pragma unroll
        for (int pp = 0; pp < 4; pp++) {
            int idx = t + pp * 256;
            int r = idx >> 3, c = (idx & 7) * 8;
            CP16(smaddr(Ad + r * 72 + c), g_O16 + (size_t)(m0 + r) * Dd + k0 + c);
        }
#pragma unroll
        for (int pp = 0; pp < 4; pp++) {
            int idx = t + pp * 256;
            int r = idx >> 4, c = (idx & 15) * 8;
            CP16(smaddr(Bd + r * 136 + c), g_Wfc16 + (size_t)(k0 + r) * Dd + n0 + c);
        }
    };

    load_stage(0, 0);
    CP_COMMIT();

    for (int s = 0; s < 16; s++) {
        int cur = s & 1;
        if (s < 15) { load_stage((s + 1) * 64, cur ^ 1); CP_COMMIT(); CP_WAIT1(); }
        else        { CP_WAIT0(); }
        __syncthreads();

        const __half* Ac = As + cur * A_ST;
        const __half* Bc = Bs + cur * B_ST;
#pragma unroll
        for (int ks = 0; ks < 4; ks++) {
            int kk = ks * 16;
            uint32_t a[2][4];
#pragma unroll
            for (int mt = 0; mt < 2; mt++)
                ldsm4(a[mt][0], a[mt][1], a[mt][2], a[mt][3],
                      smaddr(Ac + (wm * 32 + mt * 16 + (lane & 15)) * 72 + kk + ((lane >> 4) << 3)));
            uint32_t bf[8][2];
#pragma unroll
            for (int nb = 0; nb < 4; nb++) {
                int nn0 = wn * 64 + nb * 16;
                uint32_t r0, r1, r2, r3;
                ldsm4t(r0, r1, r2, r3,
                       smaddr(Bc + (kk + ((lane >> 3) & 1) * 8 + (lane & 7)) * 136 + nn0 + (lane >> 4) * 8));
                bf[nb * 2][0] = r0; bf[nb * 2][1] = r1;
                bf[nb * 2 + 1][0] = r2; bf[nb * 2 + 1][1] = r3;
            }
#pragma unroll
            for (int mt = 0; mt < 2; mt++)
#pragma unroll
                for (int nt = 0; nt < 8; nt++)
                    mma16(acc[mt][nt], a[mt], bf[nt]);
        }
        __syncthreads();
    }

#pragma unroll
    for (int mt = 0; mt < 2; mt++) {
#pragma unroll
        for (int half = 0; half < 2; half++) {
            int r = m0 + wm * 32 + mt * 16 + g + half * 8;
            float* dst = out + (size_t)r * Dd + n0;
#pragma unroll
            for (int nt = 0; nt < 8; nt++) {
                int cc = wn * 64 + nt * 8 + 2 * tg;
                float2 v;
                v.x = acc[mt][nt][half * 2 + 0] + bfc[n0 + cc];
                v.y = acc[mt][nt][half * 2 + 1] + bfc[n0 + cc + 1];
                *(float2*)(dst + cc) = v;
            }
        }
    }
}

// ============================================================
extern "C" void kernel_launch(void* const* d_in, const int* in_sizes, int n_in,
                              void* d_out, int out_size)
{
    const float* x      = (const float*)d_in[0];
    const int*   x_mask = (const int*)  d_in[1];
    const float* Wq     = (const float*)d_in[2];
    const float* bq     = (const float*)d_in[3];
    const float* Wk     = (const float*)d_in[4];
    const float* bk     = (const float*)d_in[5];
    const float* Wv     = (const float*)d_in[6];
    const float* bv     = (const float*)d_in[7];
    const float* Wfc    = (const float*)d_in[8];
    const float* bfc    = (const float*)d_in[9];
    float* out = (float*)d_out;

    static bool attr_done = false;
    if (!attr_done) {
        cudaFuncSetAttribute(attn_kernel, cudaFuncAttributeMaxDynamicSharedMemorySize, ATTN_SMEM_BYTES);
        cudaFuncSetAttribute(qkv_gemm,    cudaFuncAttributeMaxDynamicSharedMemorySize, GEMM_SMEM);
        cudaFuncSetAttribute(fc_gemm,     cudaFuncAttributeMaxDynamicSharedMemorySize, GEMM_SMEM);
        attr_done = true;
    }

    convert_all<<<2048, 256>>>(x, Wq, Wk, Wv, Wfc);
    qkv_gemm<<<dim3(128, 1, 24), 256, GEMM_SMEM>>>(bq, bk, bv);
    attn_kernel<<<dim3(8, 8, 16), 256, ATTN_SMEM_BYTES>>>(x_mask);
    fc_gemm<<<dim3(128, 8, 1), 256, GEMM_SMEM>>>(bfc, out);
}